// round 16
// baseline (speedup 1.0000x reference)
#include <cuda_runtime.h>
#include <cstdint>

#define BB    256
#define TT    256
#define DD    128
#define HH    384
#define LL    12
#define GG    1560
#define NPAD  1792
#define MT    64
#define NTX   64           // xpre N-tile (28 tiles)
#define NTS   48           // scan N-tile (37 tiles)
#define GRIDC 148          // 4 m-groups x 37 n-tiles
#define NMEM  37
#define ASTRIDE 386        // 384 + 2
#define XSTRIDE 130        // 128 + 2
#define XPSTRIDE 52        // 48 + 4 pad
#define FULLMASK 0xffffffffu

#define SCAN_SMEM (((MT + NTS) * ASTRIDE + MT * XPSTRIDE) * 4)   // 186240 B
#define XPRE_SMEM ((MT * XSTRIDE + NTX * XSTRIDE) * 4)           // 66560 B

__device__ __align__(16) float g_Wc[(DD + HH) * NPAD];
__device__ __align__(16) float g_wt[NPAD];
__device__ __align__(16) float g_bias[NPAD];
__device__ __align__(16) float g_xpre[(size_t)BB * TT * NPAD];  // [t][b][n]
__device__ __align__(16) float g_h[BB * HH];
__device__ __align__(16) float g_c[BB * HH];
__device__ __align__(16) float g_xout[BB * NPAD];
__device__ unsigned g_cnt4[4 * 32];              // per-group arrival counters (128B apart)
__device__ volatile unsigned g_rel4[4 * 32];     // per-group release words

#define FFMA2(acc, a, b) \
    asm("fma.rn.f32x2 %0, %1, %2, %0;" : "+l"(acc) : "l"(a), "l"(b))
#define UNPK(v, lo, hi) \
    asm("mov.b64 {%0, %1}, %2;" : "=f"(lo), "=f"(hi) : "l"(v))

__device__ __forceinline__ float fast_tanh(float x) {
    float r;
    asm("tanh.approx.f32 %0, %1;" : "=f"(r) : "f"(x));
    return r;
}
__device__ __forceinline__ float fsig(float x) {
    return fmaf(fast_tanh(0.5f * x), 0.5f, 0.5f);
}
__device__ __forceinline__ float ftanh(float x) { return fast_tanh(x); }

__device__ __forceinline__ float warpMax(float v) {
    #pragma unroll
    for (int o = 16; o > 0; o >>= 1) v = fmaxf(v, __shfl_xor_sync(FULLMASK, v, o));
    return v;
}
__device__ __forceinline__ float warpSum(float v) {
    #pragma unroll
    for (int o = 16; o > 0; o >>= 1) v += __shfl_xor_sync(FULLMASK, v, o);
    return v;
}

// Proven R7-pattern barrier, one independent instance per group of 37 CTAs.
__device__ __forceinline__ void group_barrier(int grp, unsigned gen) {
    __threadfence();
    __syncthreads();
    if (threadIdx.x == 0) {
        unsigned prev = atomicAdd(&g_cnt4[grp * 32], 1u);
        if (prev == gen * NMEM - 1u) {
            g_rel4[grp * 32] = gen;
            __threadfence();
        } else {
            while (g_rel4[grp * 32] < gen) { }
            __threadfence();
        }
    }
    __syncthreads();
}

__global__ void prep_kernel(const float* __restrict__ Wk,
                            const float* __restrict__ bk,
                            const float* __restrict__ Wr,
                            const float* __restrict__ br) {
    int i = blockIdx.x * blockDim.x + threadIdx.x;
    int stride = gridDim.x * blockDim.x;
    if (i < 4 * 32) { g_cnt4[i] = 0u; g_rel4[i] = 0u; }
    for (int j = i; j < BB * HH; j += stride) { g_h[j] = 0.f; g_c[j] = 0.f; }
    for (int j = i; j < (DD + HH) * NPAD; j += stride) {
        int k = j / NPAD, n = j - k * NPAD;
        float v = 0.f;
        if (n < GG) v = (k < DD) ? Wk[k * GG + n] : Wr[(k - DD) * GG + n];
        g_Wc[j] = v;
    }
    for (int n = i; n < NPAD; n += stride) {
        g_wt[n]   = (n < GG) ? (Wk[DD * GG + n] + Wr[HH * GG + n]) : 0.f;
        g_bias[n] = (n < GG) ? (bk[n] + br[n]) : 0.f;
    }
}

// Fully parallel, barrier-free: xpre[t][b][:] = x[b,t,:] @ Wk + time*wt + bias (K=128)
__global__ void __launch_bounds__(256)
xpre_kernel(const float* __restrict__ x, const float* __restrict__ time) {
    extern __shared__ float sm[];
    float* As  = sm;                     // [MT][XSTRIDE]
    float* Bsm = sm + MT * XSTRIDE;      // [NTX][XSTRIDE] (transposed Wk)

    const int tid = threadIdx.x;
    const int n0  = blockIdx.x * NTX;
    const int t   = blockIdx.y >> 2;
    const int b0  = (blockIdx.y & 3) * MT;

    const int tm = tid & 15, tn = tid >> 4;

    for (int idx = tid; idx < NTX * DD; idx += 256) {
        int k = idx >> 6;
        int n = idx & 63;
        Bsm[n * XSTRIDE + k] = g_Wc[(size_t)k * NPAD + n0 + n];
    }
    for (int q = tid; q < MT * (DD / 4); q += 256) {
        int row = q >> 5;
        int kq  = q & 31;
        float4 v = *reinterpret_cast<const float4*>(
            &x[((size_t)(b0 + row) * TT + t) * DD + 4 * kq]);
        float* dst = &As[row * XSTRIDE + 4 * kq];
        *reinterpret_cast<float2*>(dst)     = make_float2(v.x, v.y);
        *reinterpret_cast<float2*>(dst + 2) = make_float2(v.z, v.w);
    }
    __syncthreads();

    unsigned long long acc[4][4];
    #pragma unroll
    for (int i = 0; i < 4; ++i)
        #pragma unroll
        for (int j = 0; j < 4; ++j) acc[i][j] = 0ull;

    const float* ap0 = As + tm * XSTRIDE;
    const float* bp0 = Bsm + 4 * tn * XSTRIDE;

    #pragma unroll 8
    for (int k = 0; k < DD; k += 2) {
        unsigned long long a0 = *reinterpret_cast<const unsigned long long*>(ap0 + 0 * 16 * XSTRIDE + k);
        unsigned long long a1 = *reinterpret_cast<const unsigned long long*>(ap0 + 1 * 16 * XSTRIDE + k);
        unsigned long long a2 = *reinterpret_cast<const unsigned long long*>(ap0 + 2 * 16 * XSTRIDE + k);
        unsigned long long a3 = *reinterpret_cast<const unsigned long long*>(ap0 + 3 * 16 * XSTRIDE + k);
        unsigned long long b0v = *reinterpret_cast<const unsigned long long*>(bp0 + 0 * XSTRIDE + k);
        unsigned long long b1v = *reinterpret_cast<const unsigned long long*>(bp0 + 1 * XSTRIDE + k);
        unsigned long long b2v = *reinterpret_cast<const unsigned long long*>(bp0 + 2 * XSTRIDE + k);
        unsigned long long b3v = *reinterpret_cast<const unsigned long long*>(bp0 + 3 * XSTRIDE + k);
        FFMA2(acc[0][0], a0, b0v); FFMA2(acc[0][1], a0, b1v);
        FFMA2(acc[0][2], a0, b2v); FFMA2(acc[0][3], a0, b3v);
        FFMA2(acc[1][0], a1, b0v); FFMA2(acc[1][1], a1, b1v);
        FFMA2(acc[1][2], a1, b2v); FFMA2(acc[1][3], a1, b3v);
        FFMA2(acc[2][0], a2, b0v); FFMA2(acc[2][1], a2, b1v);
        FFMA2(acc[2][2], a2, b2v); FFMA2(acc[2][3], a2, b3v);
        FFMA2(acc[3][0], a3, b0v); FFMA2(acc[3][1], a3, b1v);
        FFMA2(acc[3][2], a3, b2v); FFMA2(acc[3][3], a3, b3v);
    }

    const int c0 = n0 + 4 * tn;
    float4 wt4 = *reinterpret_cast<const float4*>(&g_wt[c0]);
    float4 bi4 = *reinterpret_cast<const float4*>(&g_bias[c0]);
    #pragma unroll
    for (int mi = 0; mi < 4; ++mi) {
        int b = b0 + tm + 16 * mi;
        float tt = time[(size_t)b * TT + t];
        float lo, hi, v0, v1, v2, v3;
        UNPK(acc[mi][0], lo, hi); v0 = lo + hi;
        UNPK(acc[mi][1], lo, hi); v1 = lo + hi;
        UNPK(acc[mi][2], lo, hi); v2 = lo + hi;
        UNPK(acc[mi][3], lo, hi); v3 = lo + hi;
        float4 o;
        o.x = v0 + tt * wt4.x + bi4.x;
        o.y = v1 + tt * wt4.y + bi4.y;
        o.z = v2 + tt * wt4.z + bi4.z;
        o.w = v3 + tt * wt4.w + bi4.w;
        *reinterpret_cast<float4*>(&g_xpre[((size_t)t * BB + b) * NPAD + c0]) = o;
    }
}

// Persistent scan: 4 decoupled groups of 37 CTAs, group-scoped barriers,
// stationary Wr in smem, cp.async xpre prefetch, MUFU activations.
__global__ void __launch_bounds__(256, 1)
scan_kernel(float* __restrict__ out) {
    extern __shared__ float sm[];
    float* As  = sm;                           // [MT][ASTRIDE]
    float* Bsm = sm + MT * ASTRIDE;            // [NTS][ASTRIDE] (transposed Wr)
    float* Xp  = sm + (MT + NTS) * ASTRIDE;    // [MT][XPSTRIDE]
    __shared__ float s_fm[2][LL], s_im[2][LL];

    const int tid = threadIdx.x;
    const int cta = blockIdx.x;
    const int grp = cta & 3;
    const int mem = cta >> 2;
    const int m0 = grp * MT;
    const int n0 = mem * NTS;

    const int tm = tid & 15, tn = tid >> 4;
    const int wid = tid >> 5, lid = tid & 31;

    // group-local gate assignment: member 'mem' handles rows [r0o, r1o) of its group
    const int bstart = m0 + (mem * MT) / NMEM;
    const int bend   = m0 + ((mem + 1) * MT) / NMEM;
    const int nb     = bend - bstart;   // 1 or 2

    // stage B (Wr tile, transposed) ONCE
    for (int idx = tid; idx < NTS * HH; idx += 256) {
        int k = idx / NTS;
        int n = idx - k * NTS;
        Bsm[n * ASTRIDE + k] = g_Wc[(size_t)(DD + k) * NPAD + n0 + n];
    }
    __syncthreads();

    const float* ap0 = As + tm * ASTRIDE;
    const float* bp0 = Bsm + 3 * tn * ASTRIDE;

    unsigned gen = 0;

    for (int t = 0; t < TT; ++t) {
        // async prefetch xpre tile — hidden behind GEMM
        {
            const float* base = g_xpre + ((size_t)t * BB + m0) * NPAD + n0;
            for (int q = tid; q < MT * 12; q += 256) {
                int row = q / 12;
                int c4  = q - row * 12;
                unsigned dst = (unsigned)__cvta_generic_to_shared(
                    &Xp[row * XPSTRIDE + 4 * c4]);
                const float* src = base + (size_t)row * NPAD + 4 * c4;
                asm volatile("cp.async.cg.shared.global [%0], [%1], 16;"
                             :: "r"(dst), "l"(src) : "memory");
            }
            asm volatile("cp.async.commit_group;" ::: "memory");
        }

        // stage A = h tile
        for (int q = tid; q < MT * (HH / 4); q += 256) {
            int row = q / 96;
            int kq  = q - row * 96;
            float4 v = __ldcg(reinterpret_cast<const float4*>(
                &g_h[(m0 + row) * HH + 4 * kq]));
            float* dst = &As[row * ASTRIDE + 4 * kq];
            *reinterpret_cast<float2*>(dst)     = make_float2(v.x, v.y);
            *reinterpret_cast<float2*>(dst + 2) = make_float2(v.z, v.w);
        }
        __syncthreads();

        unsigned long long acc[4][3];
        #pragma unroll
        for (int i = 0; i < 4; ++i)
            #pragma unroll
            for (int j = 0; j < 3; ++j) acc[i][j] = 0ull;

        #pragma unroll 8
        for (int k = 0; k < HH; k += 2) {
            unsigned long long a0 = *reinterpret_cast<const unsigned long long*>(ap0 + 0 * 16 * ASTRIDE + k);
            unsigned long long a1 = *reinterpret_cast<const unsigned long long*>(ap0 + 1 * 16 * ASTRIDE + k);
            unsigned long long a2 = *reinterpret_cast<const unsigned long long*>(ap0 + 2 * 16 * ASTRIDE + k);
            unsigned long long a3 = *reinterpret_cast<const unsigned long long*>(ap0 + 3 * 16 * ASTRIDE + k);
            unsigned long long b0v = *reinterpret_cast<const unsigned long long*>(bp0 + 0 * ASTRIDE + k);
            unsigned long long b1v = *reinterpret_cast<const unsigned long long*>(bp0 + 1 * ASTRIDE + k);
            unsigned long long b2v = *reinterpret_cast<const unsigned long long*>(bp0 + 2 * ASTRIDE + k);
            FFMA2(acc[0][0], a0, b0v); FFMA2(acc[0][1], a0, b1v); FFMA2(acc[0][2], a0, b2v);
            FFMA2(acc[1][0], a1, b0v); FFMA2(acc[1][1], a1, b1v); FFMA2(acc[1][2], a1, b2v);
            FFMA2(acc[2][0], a2, b0v); FFMA2(acc[2][1], a2, b1v); FFMA2(acc[2][2], a2, b2v);
            FFMA2(acc[3][0], a3, b0v); FFMA2(acc[3][1], a3, b1v); FFMA2(acc[3][2], a3, b2v);
        }

        // wait prefetch, then epilogue: x_out = acc + Xp (smem)
        asm volatile("cp.async.wait_group 0;" ::: "memory");
        __syncthreads();
        {
            const int c0 = n0 + 3 * tn;
            #pragma unroll
            for (int mi = 0; mi < 4; ++mi) {
                int rloc = tm + 16 * mi;
                int row  = m0 + rloc;
                const float* xp = &Xp[rloc * XPSTRIDE + 3 * tn];
                float* dst = &g_xout[(size_t)row * NPAD + c0];
                float lo, hi;
                UNPK(acc[mi][0], lo, hi); dst[0] = lo + hi + xp[0];
                UNPK(acc[mi][1], lo, hi); dst[1] = lo + hi + xp[1];
                UNPK(acc[mi][2], lo, hi); dst[2] = lo + hi + xp[2];
            }
        }

        group_barrier(grp, ++gen);

        // gates: warp w does softmax for batch bstart+w (group-local rows)
        if (wid < nb) {
            const int b = bstart + wid;
            const float* xr = g_xout + (size_t)b * NPAD;
            int l = lid;
            float z1 = (l < LL) ? __ldcg(xr + l)      : -3.0e38f;
            float z2 = (l < LL) ? __ldcg(xr + LL + l) : -3.0e38f;
            float m1 = warpMax(z1), m2 = warpMax(z2);
            float p1 = (l < LL) ? __expf(z1 - m1) : 0.f;
            float p2 = (l < LL) ? __expf(z2 - m2) : 0.f;
            float s1 = warpSum(p1), s2 = warpSum(p2);
            p1 /= s1; p2 /= s2;
            float q1 = p1, q2 = p2;
            #pragma unroll
            for (int o = 1; o < 16; o <<= 1) {
                float u1 = __shfl_up_sync(FULLMASK, q1, o);
                float u2 = __shfl_up_sync(FULLMASK, q2, o);
                if (l >= o) { q1 += u1; q2 += u2; }
            }
            if (l < LL) {
                s_fm[wid][l] = q1;                 // l2r cumax (inclusive prefix)
                s_im[wid][l] = 1.0f - (q2 - p2);   // r2l cumax (inclusive suffix)
            }
        }
        __syncthreads();

        // flat gate/state loop (HW tanh activations)
        for (int idx = tid; idx < nb * HH; idx += 256) {
            int bi = idx / HH;
            int e  = idx - bi * HH;
            int b  = bstart + bi;
            const float* gr = g_xout + (size_t)b * NPAD + 2 * LL;
            float f  = fsig(__ldcg(gr + e));
            float ig = fsig(__ldcg(gr + HH + e));
            float o  = fsig(__ldcg(gr + 2 * HH + e));
            float ci = ftanh(__ldcg(gr + 3 * HH + e));
            int   l  = e >> 5;
            float fm = s_fm[bi][l], im = s_im[bi][l];
            float ov = fm * im;
            float cl = g_c[b * HH + e];
            float cn = ov * (f * cl + ig * ci) + (fm - ov) * cl + (im - ov) * ci;
            float hn = o * ftanh(cn);
            g_c[b * HH + e] = cn;
            g_h[b * HH + e] = hn;
            out[((size_t)b * TT + t) * HH + e] = hn;
        }

        group_barrier(grp, ++gen);
    }
}

extern "C" void kernel_launch(void* const* d_in, const int* in_sizes, int n_in,
                              void* d_out, int out_size) {
    const float* x    = (const float*)d_in[0];
    const float* time = (const float*)d_in[1];
    const float* Wk   = (const float*)d_in[2];
    const float* bk   = (const float*)d_in[3];
    const float* Wr   = (const float*)d_in[4];
    const float* br   = (const float*)d_in[5];
    float* out = (float*)d_out;

    cudaFuncSetAttribute(scan_kernel,
                         cudaFuncAttributeMaxDynamicSharedMemorySize, SCAN_SMEM);
    cudaFuncSetAttribute(xpre_kernel,
                         cudaFuncAttributeMaxDynamicSharedMemorySize, XPRE_SMEM);

    prep_kernel<<<512, 256>>>(Wk, bk, Wr, br);
    xpre_kernel<<<dim3(28, (BB * TT) / MT), 256, XPRE_SMEM>>>(x, time);
    scan_kernel<<<GRIDC, 256, SCAN_SMEM>>>(out);
}

// round 17
// speedup vs baseline: 1.2953x; 1.2953x over previous
#include <cuda_runtime.h>
#include <cuda_bf16.h>
#include <cstdint>

#define BB    256
#define TT    256
#define DD    128
#define HH    384
#define LL    12
#define GG    1560
#define NPAD  1792
#define MT    64
#define NTX   64           // xpre N-tile (28 tiles)
#define NTS   48           // scan N-tile (37 tiles)
#define GRIDC 148          // 4 m-tiles x 37 n-tiles
#define XSTRIDE 130        // 128 + 2
#define XPSTRIDE 52        // 48 + 4 pad
#define FULLMASK 0xffffffffu

// scan smem: Apack u32[2][4][24][128] + Bpack u32[2][2][24][3][64] + Xp f32[64][52]
#define AP_WORDS  (2 * 4 * 24 * 128)      // 24576
#define BP_WORDS  (2 * 2 * 24 * 3 * 64)   // 18432
#define XP_WORDS  (MT * XPSTRIDE)         // 3328
#define SCAN_SMEM ((AP_WORDS + BP_WORDS + XP_WORDS) * 4)   // 185344 B
#define XPRE_SMEM ((MT * XSTRIDE + NTX * XSTRIDE) * 4)     // 66560 B

__device__ __align__(16) float g_Wc[(DD + HH) * NPAD];  // rows 0..127 Wk, 128..511 Wr
__device__ __align__(16) float g_wt[NPAD];
__device__ __align__(16) float g_bias[NPAD];
__device__ __align__(16) float g_xpre[(size_t)BB * TT * NPAD];  // [t][b][n]
__device__ __align__(16) float g_h[BB * HH];
__device__ __align__(16) float g_c[BB * HH];
__device__ __align__(16) float g_xout[BB * NPAD];
__device__ unsigned g_bar_arrive;
__device__ volatile unsigned g_bar_release;

#define FFMA2(acc, a, b) \
    asm("fma.rn.f32x2 %0, %1, %2, %0;" : "+l"(acc) : "l"(a), "l"(b))
#define UNPK(v, lo, hi) \
    asm("mov.b64 {%0, %1}, %2;" : "=f"(lo), "=f"(hi) : "l"(v))

__device__ __forceinline__ float fast_tanh(float x) {
    float r;
    asm("tanh.approx.f32 %0, %1;" : "=f"(r) : "f"(x));
    return r;
}
__device__ __forceinline__ float fsig(float x) {
    return fmaf(fast_tanh(0.5f * x), 0.5f, 0.5f);
}
__device__ __forceinline__ float ftanh(float x) { return fast_tanh(x); }

__device__ __forceinline__ float warpMax(float v) {
    #pragma unroll
    for (int o = 16; o > 0; o >>= 1) v = fmaxf(v, __shfl_xor_sync(FULLMASK, v, o));
    return v;
}
__device__ __forceinline__ float warpSum(float v) {
    #pragma unroll
    for (int o = 16; o > 0; o >>= 1) v += __shfl_xor_sync(FULLMASK, v, o);
    return v;
}

// pack two floats as bf16x2 (low half = first element)
__device__ __forceinline__ unsigned pack_bf16(float f0, float f1) {
    unsigned r;
    asm("cvt.rn.bf16x2.f32 %0, %1, %2;" : "=r"(r) : "f"(f1), "f"(f0));
    return r;
}
// hi/lo split of a float pair into two bf16x2 words
__device__ __forceinline__ void split_pair(float f0, float f1,
                                           unsigned& hi, unsigned& lo) {
    __nv_bfloat16 h0 = __float2bfloat16(f0);
    __nv_bfloat16 h1 = __float2bfloat16(f1);
    float r0 = f0 - __bfloat162float(h0);
    float r1 = f1 - __bfloat162float(h1);
    unsigned u0 = (unsigned)__bfloat16_as_ushort(h0);
    unsigned u1 = (unsigned)__bfloat16_as_ushort(h1);
    hi = u0 | (u1 << 16);
    lo = pack_bf16(r0, r1);
}

#define MMA_BF16(d0, d1, d2, d3, a0, a1, a2, a3, b0, b1) \
    asm volatile("mma.sync.aligned.m16n8k16.row.col.f32.bf16.bf16.f32 " \
        "{%0,%1,%2,%3}, {%4,%5,%6,%7}, {%8,%9}, {%0,%1,%2,%3};" \
        : "+f"(d0), "+f"(d1), "+f"(d2), "+f"(d3) \
        : "r"(a0), "r"(a1), "r"(a2), "r"(a3), "r"(b0), "r"(b1))

// Proven R2/R7/R15 grid barrier: atomicAdd arrivals + volatile release flag.
__device__ __forceinline__ void grid_barrier(unsigned gen) {
    __threadfence();
    __syncthreads();
    if (threadIdx.x == 0) {
        unsigned prev = atomicAdd(&g_bar_arrive, 1u);
        if (prev == gen * GRIDC - 1u) {
            g_bar_release = gen;
            __threadfence();
        } else {
            while (g_bar_release < gen) { }
            __threadfence();
        }
    }
    __syncthreads();
}

__global__ void prep_kernel(const float* __restrict__ Wk,
                            const float* __restrict__ bk,
                            const float* __restrict__ Wr,
                            const float* __restrict__ br) {
    int i = blockIdx.x * blockDim.x + threadIdx.x;
    int stride = gridDim.x * blockDim.x;
    if (i == 0) { g_bar_arrive = 0u; g_bar_release = 0u; }
    for (int j = i; j < BB * HH; j += stride) { g_h[j] = 0.f; g_c[j] = 0.f; }
    for (int j = i; j < (DD + HH) * NPAD; j += stride) {
        int k = j / NPAD, n = j - k * NPAD;
        float v = 0.f;
        if (n < GG) v = (k < DD) ? Wk[k * GG + n] : Wr[(k - DD) * GG + n];
        g_Wc[j] = v;
    }
    for (int n = i; n < NPAD; n += stride) {
        g_wt[n]   = (n < GG) ? (Wk[DD * GG + n] + Wr[HH * GG + n]) : 0.f;
        g_bias[n] = (n < GG) ? (bk[n] + br[n]) : 0.f;
    }
}

// Fully parallel, barrier-free: xpre[t][b][:] = x[b,t,:] @ Wk + time*wt + bias (K=128)
__global__ void __launch_bounds__(256)
xpre_kernel(const float* __restrict__ x, const float* __restrict__ time) {
    extern __shared__ float sm[];
    float* As  = sm;                     // [MT][XSTRIDE]
    float* Bsm = sm + MT * XSTRIDE;      // [NTX][XSTRIDE] (transposed Wk)

    const int tid = threadIdx.x;
    const int n0  = blockIdx.x * NTX;
    const int t   = blockIdx.y >> 2;
    const int b0  = (blockIdx.y & 3) * MT;

    const int tm = tid & 15, tn = tid >> 4;

    for (int idx = tid; idx < NTX * DD; idx += 256) {
        int k = idx >> 6;
        int n = idx & 63;
        Bsm[n * XSTRIDE + k] = g_Wc[(size_t)k * NPAD + n0 + n];
    }
    for (int q = tid; q < MT * (DD / 4); q += 256) {
        int row = q >> 5;
        int kq  = q & 31;
        float4 v = *reinterpret_cast<const float4*>(
            &x[((size_t)(b0 + row) * TT + t) * DD + 4 * kq]);
        float* dst = &As[row * XSTRIDE + 4 * kq];
        *reinterpret_cast<float2*>(dst)     = make_float2(v.x, v.y);
        *reinterpret_cast<float2*>(dst + 2) = make_float2(v.z, v.w);
    }
    __syncthreads();

    unsigned long long acc[4][4];
    #pragma unroll
    for (int i = 0; i < 4; ++i)
        #pragma unroll
        for (int j = 0; j < 4; ++j) acc[i][j] = 0ull;

    const float* ap0 = As + tm * XSTRIDE;
    const float* bp0 = Bsm + 4 * tn * XSTRIDE;

    #pragma unroll 8
    for (int k = 0; k < DD; k += 2) {
        unsigned long long a0 = *reinterpret_cast<const unsigned long long*>(ap0 + 0 * 16 * XSTRIDE + k);
        unsigned long long a1 = *reinterpret_cast<const unsigned long long*>(ap0 + 1 * 16 * XSTRIDE + k);
        unsigned long long a2 = *reinterpret_cast<const unsigned long long*>(ap0 + 2 * 16 * XSTRIDE + k);
        unsigned long long a3 = *reinterpret_cast<const unsigned long long*>(ap0 + 3 * 16 * XSTRIDE + k);
        unsigned long long b0v = *reinterpret_cast<const unsigned long long*>(bp0 + 0 * XSTRIDE + k);
        unsigned long long b1v = *reinterpret_cast<const unsigned long long*>(bp0 + 1 * XSTRIDE + k);
        unsigned long long b2v = *reinterpret_cast<const unsigned long long*>(bp0 + 2 * XSTRIDE + k);
        unsigned long long b3v = *reinterpret_cast<const unsigned long long*>(bp0 + 3 * XSTRIDE + k);
        FFMA2(acc[0][0], a0, b0v); FFMA2(acc[0][1], a0, b1v);
        FFMA2(acc[0][2], a0, b2v); FFMA2(acc[0][3], a0, b3v);
        FFMA2(acc[1][0], a1, b0v); FFMA2(acc[1][1], a1, b1v);
        FFMA2(acc[1][2], a1, b2v); FFMA2(acc[1][3], a1, b3v);
        FFMA2(acc[2][0], a2, b0v); FFMA2(acc[2][1], a2, b1v);
        FFMA2(acc[2][2], a2, b2v); FFMA2(acc[2][3], a2, b3v);
        FFMA2(acc[3][0], a3, b0v); FFMA2(acc[3][1], a3, b1v);
        FFMA2(acc[3][2], a3, b2v); FFMA2(acc[3][3], a3, b3v);
    }

    const int c0 = n0 + 4 * tn;
    float4 wt4 = *reinterpret_cast<const float4*>(&g_wt[c0]);
    float4 bi4 = *reinterpret_cast<const float4*>(&g_bias[c0]);
    #pragma unroll
    for (int mi = 0; mi < 4; ++mi) {
        int b = b0 + tm + 16 * mi;
        float tt = time[(size_t)b * TT + t];
        float lo, hi, v0, v1, v2, v3;
        UNPK(acc[mi][0], lo, hi); v0 = lo + hi;
        UNPK(acc[mi][1], lo, hi); v1 = lo + hi;
        UNPK(acc[mi][2], lo, hi); v2 = lo + hi;
        UNPK(acc[mi][3], lo, hi); v3 = lo + hi;
        float4 o;
        o.x = v0 + tt * wt4.x + bi4.x;
        o.y = v1 + tt * wt4.y + bi4.y;
        o.z = v2 + tt * wt4.z + bi4.z;
        o.w = v3 + tt * wt4.w + bi4.w;
        *reinterpret_cast<float4*>(&g_xpre[((size_t)t * BB + b) * NPAD + c0]) = o;
    }
}

// Persistent scan: tensor-core bf16-split GEMM (3xBF16), stationary fragment-packed
// Wr in smem, cp.async xpre prefetch, MUFU gates, flat grid barrier.
__global__ void __launch_bounds__(256, 1)
scan_kernel(float* __restrict__ out) {
    extern __shared__ float sm[];
    unsigned* Ap = reinterpret_cast<unsigned*>(sm);        // [2][4][24][128]
    unsigned* Bp = Ap + AP_WORDS;                          // [2][2][24][3][64]
    float*    Xp = reinterpret_cast<float*>(Bp + BP_WORDS); // [64][52]
    __shared__ float s_fm[2][LL], s_im[2][LL];

    const int tid = threadIdx.x;
    const int cta = blockIdx.x;
    const int m0 = (cta & 3) * MT;
    const int n0 = (cta >> 2) * NTS;

    const int wid = tid >> 5, lid = tid & 31;
    const int gid = lid >> 2, tid4 = lid & 3;

    const int bstart = (cta * BB) / GRIDC;
    const int bend   = ((cta + 1) * BB) / GRIDC;
    const int nb     = bend - bstart;   // 1 or 2

    // ---- convert Wr tile into fragment-packed bf16 hi/lo (ONCE) ----
    // slot space: nh(2) x ks(24) x tile(3) x lane2(64)
    for (int slot = tid; slot < 2 * 24 * 3 * 64; slot += 256) {
        int lane2 = slot & 63;
        int lane  = lane2 >> 1;
        int rreg  = lane2 & 1;
        int tmp   = slot >> 6;
        int tile  = tmp % 3;  tmp /= 3;
        int ks    = tmp % 24;
        int nh    = tmp / 24;
        int g  = lane >> 2, t4 = lane & 3;
        int n  = n0 + (nh * 3 + tile) * 8 + g;
        int k0 = 16 * ks + 8 * rreg + 2 * t4;
        float w0 = g_Wc[(size_t)(DD + k0) * NPAD + n];
        float w1 = g_Wc[(size_t)(DD + k0 + 1) * NPAD + n];
        unsigned hi, lo;
        split_pair(w0, w1, hi, lo);
        int base = ((nh * 24 + ks) * 3 + tile) * 64 + lane2;
        Bp[base] = hi;                       // pass 0
        Bp[(2 * 24 * 3 * 64) + base] = lo;   // pass 1 (offset = half of BP_WORDS)
    }
    __syncthreads();

    const int mw = wid & 3;    // m-block (16 rows)
    const int nh = wid >> 2;   // n-half (3 tiles of 8)

    unsigned gen = 0;

    for (int t = 0; t < TT; ++t) {
        // async prefetch xpre tile — hidden behind staging+GEMM
        {
            const float* base = g_xpre + ((size_t)t * BB + m0) * NPAD + n0;
            for (int q = tid; q < MT * 12; q += 256) {
                int row = q / 12;
                int c4  = q - row * 12;
                unsigned dst = (unsigned)__cvta_generic_to_shared(
                    &Xp[row * XPSTRIDE + 4 * c4]);
                const float* src = base + (size_t)row * NPAD + 4 * c4;
                asm volatile("cp.async.cg.shared.global [%0], [%1], 16;"
                             :: "r"(dst), "l"(src) : "memory");
            }
            asm volatile("cp.async.commit_group;" ::: "memory");
        }

        // stage A: read h (coalesced float4), split to bf16 hi/lo fragments
        for (int q = tid; q < MT * (HH / 4); q += 256) {
            int row = q / 96;
            int kq  = q - row * 96;
            float4 v = __ldcg(reinterpret_cast<const float4*>(
                &g_h[(m0 + row) * HH + 4 * kq]));
            int amw  = row >> 4;
            int rr   = row & 15;
            int ag   = rr & 7;
            int up   = rr >> 3;
            // two k-pairs: p0 = 2kq (v.x,v.y), p1 = 2kq+1 (v.z,v.w)
            #pragma unroll
            for (int pi = 0; pi < 2; ++pi) {
                int p = 2 * kq + pi;
                float f0 = pi ? v.z : v.x;
                float f1 = pi ? v.w : v.y;
                int t4 = p & 3;
                int kh = (p >> 2) & 1;
                int ks = p >> 3;
                int lane = ag * 4 + t4;
                int reg  = up + 2 * kh;
                unsigned hi, lo;
                split_pair(f0, f1, hi, lo);
                int base = (amw * 24 + ks) * 128 + lane * 4 + reg;
                Ap[base] = hi;                      // pass 0
                Ap[(4 * 24 * 128) + base] = lo;     // pass 1
            }
        }
        __syncthreads();

        // ---- tensor-core GEMM: 3 tiles per warp, 24 k-steps, 3 passes ----
        float d[3][4];
        #pragma unroll
        for (int i = 0; i < 3; ++i)
            #pragma unroll
            for (int j = 0; j < 4; ++j) d[i][j] = 0.f;

        const unsigned* apH = Ap + (mw * 24) * 128 + lid * 4;
        const unsigned* apL = apH + 4 * 24 * 128;
        const unsigned* bpH = Bp + (nh * 24) * 3 * 64 + lid * 2;
        const unsigned* bpL = bpH + 2 * 24 * 3 * 64;

        #pragma unroll 4
        for (int ks = 0; ks < 24; ++ks) {
            uint4 ah = *reinterpret_cast<const uint4*>(apH + ks * 128);
            uint4 al = *reinterpret_cast<const uint4*>(apL + ks * 128);
            #pragma unroll
            for (int tile = 0; tile < 3; ++tile) {
                uint2 bh = *reinterpret_cast<const uint2*>(bpH + (ks * 3 + tile) * 64);
                uint2 bl = *reinterpret_cast<const uint2*>(bpL + (ks * 3 + tile) * 64);
                MMA_BF16(d[tile][0], d[tile][1], d[tile][2], d[tile][3],
                         ah.x, ah.y, ah.z, ah.w, bh.x, bh.y);
                MMA_BF16(d[tile][0], d[tile][1], d[tile][2], d[tile][3],
                         ah.x, ah.y, ah.z, ah.w, bl.x, bl.y);
                MMA_BF16(d[tile][0], d[tile][1], d[tile][2], d[tile][3],
                         al.x, al.y, al.z, al.w, bh.x, bh.y);
            }
        }

        // wait prefetch, then epilogue: x_out = D + Xp
        asm volatile("cp.async.wait_group 0;" ::: "memory");
        __syncthreads();
        {
            int rloc0 = 16 * mw + gid;
            #pragma unroll
            for (int tile = 0; tile < 3; ++tile) {
                int cc = (nh * 3 + tile) * 8 + 2 * tid4;
                float2 xp0 = *reinterpret_cast<const float2*>(&Xp[rloc0 * XPSTRIDE + cc]);
                float2 xp1 = *reinterpret_cast<const float2*>(&Xp[(rloc0 + 8) * XPSTRIDE + cc]);
                float2 o0 = make_float2(d[tile][0] + xp0.x, d[tile][1] + xp0.y);
                float2 o1 = make_float2(d[tile][2] + xp1.x, d[tile][3] + xp1.y);
                *reinterpret_cast<float2*>(&g_xout[(size_t)(m0 + rloc0) * NPAD + n0 + cc]) = o0;
                *reinterpret_cast<float2*>(&g_xout[(size_t)(m0 + rloc0 + 8) * NPAD + n0 + cc]) = o1;
            }
        }

        grid_barrier(++gen);

        // gates: warp w does softmax for batch bstart+w
        if (wid < nb) {
            const int b = bstart + wid;
            const float* xr = g_xout + (size_t)b * NPAD;
            int l = lid;
            float z1 = (l < LL) ? __ldcg(xr + l)      : -3.0e38f;
            float z2 = (l < LL) ? __ldcg(xr + LL + l) : -3.0e38f;
            float m1 = warpMax(z1), m2 = warpMax(z2);
            float p1 = (l < LL) ? __expf(z1 - m1) : 0.f;
            float p2 = (l < LL) ? __expf(z2 - m2) : 0.f;
            float s1 = warpSum(p1), s2 = warpSum(p2);
            p1 /= s1; p2 /= s2;
            float q1 = p1, q2 = p2;
            #pragma unroll
            for (int o = 1; o < 16; o <<= 1) {
                float u1 = __shfl_up_sync(FULLMASK, q1, o);
                float u2 = __shfl_up_sync(FULLMASK, q2, o);
                if (l >= o) { q1 += u1; q2 += u2; }
            }
            if (l < LL) {
                s_fm[wid][l] = q1;
                s_im[wid][l] = 1.0f - (q2 - p2);
            }
        }
        __syncthreads();

        // flat gate/state loop (HW tanh activations)
        for (int idx = tid; idx < nb * HH; idx += 256) {
            int bi = idx / HH;
            int e  = idx - bi * HH;
            int b  = bstart + bi;
            const float* gr = g_xout + (size_t)b * NPAD + 2 * LL;
            float f  = fsig(__ldcg(gr + e));
            float ig = fsig(__ldcg(gr + HH + e));
            float o  = fsig(__ldcg(gr + 2 * HH + e));
            float ci = ftanh(__ldcg(gr + 3 * HH + e));
            int   l  = e >> 5;
            float fm = s_fm[bi][l], im = s_im[bi][l];
            float ov = fm * im;
            float cl = g_c[b * HH + e];
            float cn = ov * (f * cl + ig * ci) + (fm - ov) * cl + (im - ov) * ci;
            float hn = o * ftanh(cn);
            g_c[b * HH + e] = cn;
            g_h[b * HH + e] = hn;
            out[((size_t)b * TT + t) * HH + e] = hn;
        }

        grid_barrier(++gen);
    }
}

extern "C" void kernel_launch(void* const* d_in, const int* in_sizes, int n_in,
                              void* d_out, int out_size) {
    const float* x    = (const float*)d_in[0];
    const float* time = (const float*)d_in[1];
    const float* Wk   = (const float*)d_in[2];
    const float* bk   = (const float*)d_in[3];
    const float* Wr   = (const float*)d_in[4];
    const float* br   = (const float*)d_in[5];
    float* out = (float*)d_out;

    cudaFuncSetAttribute(scan_kernel,
                         cudaFuncAttributeMaxDynamicSharedMemorySize, SCAN_SMEM);
    cudaFuncSetAttribute(xpre_kernel,
                         cudaFuncAttributeMaxDynamicSharedMemorySize, XPRE_SMEM);

    prep_kernel<<<512, 256>>>(Wk, bk, Wr, br);
    xpre_kernel<<<dim3(28, (BB * TT) / MT), 256, XPRE_SMEM>>>(x, time);
    scan_kernel<<<GRIDC, 256, SCAN_SMEM>>>(out);
}